// round 16
// baseline (speedup 1.0000x reference)
#include <cuda_runtime.h>
#include <math.h>
#include <stdint.h>

#define BB   2
#define SS   2048
#define DD   512
#define HH   8
#define DKK  64
#define BHH  (BB*HH)

// ---------------- scratch (device globals; no allocation allowed) ----------
__device__ float g_qh[BHH*SS*DKK];          // [bh][s][dk] tf32 bits, pre-scaled 1/8
__device__ float g_kh[BHH*SS*DKK];          // tf32 bits
__device__ float g_vt[BHH*DKK*SS];          // V^T [bh][dk][s], tf32 bits
__device__ float g_at[BB*SS*DD];            // attention out [b][s][h*64+dk]
__device__ float g_cos[SS*DKK];
__device__ float g_sin[SS*DKK];
__device__ float g_sc[67108864];            // scores -> unnormalized P (tf32 bits)

// ---------------- helpers ----------------------------------------------------
__device__ __forceinline__ uint32_t f2tf(float f)
{
    uint32_t u;
    asm("cvt.rna.tf32.f32 %0, %1;" : "=r"(u) : "f"(f));
    return u;
}

__device__ __forceinline__ void mma8(float* c, const uint32_t* a, const uint32_t* b)
{
    asm volatile(
        "mma.sync.aligned.m16n8k8.row.col.f32.tf32.tf32.f32 "
        "{%0,%1,%2,%3}, {%4,%5,%6,%7}, {%8,%9}, {%0,%1,%2,%3};\n"
        : "+f"(c[0]), "+f"(c[1]), "+f"(c[2]), "+f"(c[3])
        : "r"(a[0]), "r"(a[1]), "r"(a[2]), "r"(a[3]), "r"(b[0]), "r"(b[1]));
}

// ---------------- RoPE table ------------------------------------------------
__global__ void rope_tab_kernel()
{
    int idx = blockIdx.x * blockDim.x + threadIdx.x;
    if (idx >= SS * 32) return;
    int s = idx >> 5;
    int m = idx & 31;
    float f = (float)s * powf(10000.f, -(float)(2 * m) / 64.f);
    float sn, cs;
    sincosf(f, &sn, &cs);
    g_cos[s*64 + 2*m]     = cs;
    g_cos[s*64 + 2*m + 1] = cs;
    g_sin[s*64 + 2*m]     = sn;
    g_sin[s*64 + 2*m + 1] = sn;
}

// ---------------- fused QKV projection + RoPE (tf32 mma, staged q/k) ---------
#define AS(r, cc) sbuf[(r)*36 + (cc)]
#define BS(r, cc) sbuf[128*36 + (r)*36 + (cc)]

__global__ __launch_bounds__(256) void proj_kernel(
    const float* __restrict__ qx, const float* __restrict__ kx, const float* __restrict__ vx,
    const float* __restrict__ Wq, const float* __restrict__ bq,
    const float* __restrict__ Wk, const float* __restrict__ bk,
    const float* __restrict__ Wv, const float* __restrict__ bv)
{
    __shared__ uint32_t sbuf[2*128*36];   // As/Bs in mainloop; q/k staging after

    int which = blockIdx.z;
    const float* X    = (which == 0) ? qx : (which == 1) ? kx : vx;
    const float* W    = (which == 0) ? Wq : (which == 1) ? Wk : Wv;
    const float* bias = (which == 0) ? bq : (which == 1) ? bk : bv;

    int tid  = threadIdx.x;
    int wid  = tid >> 5, lane = tid & 31;
    int g    = lane >> 2, t = lane & 3;
    int wm   = wid >> 2, wn = wid & 3;
    int n0   = blockIdx.x * 128;
    int m0   = blockIdx.y * 128;

    float c[4][4][4];
    #pragma unroll
    for (int mf = 0; mf < 4; mf++)
        #pragma unroll
        for (int nf = 0; nf < 4; nf++)
            #pragma unroll
            for (int u = 0; u < 4; u++) c[mf][nf][u] = 0.f;

    int lr = tid >> 1;
    int lc = (tid & 1) * 16;

    float4 xa[4], wb[4];
    #pragma unroll
    for (int u = 0; u < 4; u++) {
        xa[u] = *(const float4*)(X + (size_t)(m0 + lr) * 512 + lc + u*4);
        wb[u] = *(const float4*)(W + (size_t)(n0 + lr) * 512 + lc + u*4);
    }
    #pragma unroll
    for (int u = 0; u < 4; u++) {
        AS(lr, lc+u*4+0) = f2tf(xa[u].x); AS(lr, lc+u*4+1) = f2tf(xa[u].y);
        AS(lr, lc+u*4+2) = f2tf(xa[u].z); AS(lr, lc+u*4+3) = f2tf(xa[u].w);
        BS(lr, lc+u*4+0) = f2tf(wb[u].x); BS(lr, lc+u*4+1) = f2tf(wb[u].y);
        BS(lr, lc+u*4+2) = f2tf(wb[u].z); BS(lr, lc+u*4+3) = f2tf(wb[u].w);
    }
    __syncthreads();

    for (int k0 = 0; k0 < 512; k0 += 32) {
        int kn = k0 + 32;
        if (kn < 512) {
            #pragma unroll
            for (int u = 0; u < 4; u++) {
                xa[u] = *(const float4*)(X + (size_t)(m0 + lr) * 512 + kn + lc + u*4);
                wb[u] = *(const float4*)(W + (size_t)(n0 + lr) * 512 + kn + lc + u*4);
            }
        }
        #pragma unroll
        for (int k8 = 0; k8 < 32; k8 += 8) {
            uint32_t a[4][4], b[4][2];
            #pragma unroll
            for (int mf = 0; mf < 4; mf++) {
                int r = wm*64 + mf*16 + g;
                a[mf][0] = AS(r, k8+t);     a[mf][1] = AS(r+8, k8+t);
                a[mf][2] = AS(r, k8+t+4);   a[mf][3] = AS(r+8, k8+t+4);
            }
            #pragma unroll
            for (int nf = 0; nf < 4; nf++) {
                int rn = wn*32 + nf*8 + g;
                b[nf][0] = BS(rn, k8+t);    b[nf][1] = BS(rn, k8+t+4);
            }
            #pragma unroll
            for (int mf = 0; mf < 4; mf++)
                #pragma unroll
                for (int nf = 0; nf < 4; nf++)
                    mma8(c[mf][nf], a[mf], b[nf]);
        }
        __syncthreads();
        if (kn < 512) {
            #pragma unroll
            for (int u = 0; u < 4; u++) {
                AS(lr, lc+u*4+0) = f2tf(xa[u].x); AS(lr, lc+u*4+1) = f2tf(xa[u].y);
                AS(lr, lc+u*4+2) = f2tf(xa[u].z); AS(lr, lc+u*4+3) = f2tf(xa[u].w);
                BS(lr, lc+u*4+0) = f2tf(wb[u].x); BS(lr, lc+u*4+1) = f2tf(wb[u].y);
                BS(lr, lc+u*4+2) = f2tf(wb[u].z); BS(lr, lc+u*4+3) = f2tf(wb[u].w);
            }
            __syncthreads();
        }
    }

    if (which == 2) {
        // ---- v epilogue: direct transposed store ----
        #pragma unroll
        for (int nf = 0; nf < 4; nf++) {
            int col = n0 + wn*32 + nf*8 + t*2;
            int hh  = col >> 6, dk = col & 63;
            float bce = bias[col], bco = bias[col+1];
            #pragma unroll
            for (int mf = 0; mf < 4; mf++) {
                #pragma unroll
                for (int half = 0; half < 2; half++) {
                    int row  = m0 + wm*64 + mf*16 + g + half*8;
                    int srow = row & (SS-1);
                    int bidx = row >> 11;
                    float e = c[mf][nf][half*2+0] + bce;
                    float o = c[mf][nf][half*2+1] + bco;
                    size_t vb = (size_t)(bidx*HH + hh) * DKK;
                    g_vt[(vb + dk    )*SS + srow] = __uint_as_float(f2tf(e));
                    g_vt[(vb + dk + 1)*SS + srow] = __uint_as_float(f2tf(o));
                }
            }
        }
    } else {
        // ---- q/k epilogue: rope + tf32 into smem stage, coalesced store ----
        float* stage = (float*)sbuf;          // [64][132]
        float* Y = (which == 0) ? g_qh : g_kh;
        float sc = (which == 0) ? 0.125f : 1.0f;

        #pragma unroll
        for (int p = 0; p < 2; p++) {
            __syncthreads();
            if (wm == p) {
                #pragma unroll
                for (int nf = 0; nf < 4; nf++) {
                    int coll = wn*32 + nf*8 + t*2;
                    int col  = n0 + coll;
                    int dk   = col & 63;
                    float bce = bias[col], bco = bias[col+1];
                    #pragma unroll
                    for (int mf = 0; mf < 4; mf++) {
                        #pragma unroll
                        for (int half = 0; half < 2; half++) {
                            int rl   = mf*16 + g + half*8;     // 0..63
                            int srow = (m0 + p*64 + rl) & (SS-1);
                            float e = c[mf][nf][half*2+0] + bce;
                            float o = c[mf][nf][half*2+1] + bco;
                            float cs = g_cos[srow*64 + dk];
                            float sn = g_sin[srow*64 + dk];
                            float ne = __uint_as_float(f2tf((e*cs - o*sn) * sc));
                            float no = __uint_as_float(f2tf((o*cs + e*sn) * sc));
                            *(float2*)&stage[rl*132 + coll] = make_float2(ne, no);
                        }
                    }
                }
            }
            __syncthreads();
            int r   = tid & 63;
            int seg = tid >> 6;
            int row  = m0 + p*64 + r;
            int srow = row & (SS-1);
            int bidx = row >> 11;
            int head = (n0 >> 6) + (seg >> 1);
            float* dst = Y + ((size_t)(bidx*HH + head)*SS + srow)*DKK + (seg & 1)*32;
            const float* src = stage + r*132 + seg*32;
            #pragma unroll
            for (int w = 0; w < 8; w++)
                ((float4*)dst)[w] = ((const float4*)src)[w];
        }
    }
}

// ---------------- output projection (tf32 mma, 64-row M-tiles) ----------------
// grid (4, 64): 256 CTAs -> fills the chip in one wave.
__global__ __launch_bounds__(256) void out_proj_kernel(
    const float* __restrict__ W, const float* __restrict__ bias, float* __restrict__ out)
{
    __shared__ uint32_t As[64][36];
    __shared__ uint32_t Bs[128][36];

    int tid  = threadIdx.x;
    int wid  = tid >> 5, lane = tid & 31;
    int g    = lane >> 2, t = lane & 3;
    int wm   = wid >> 2, wn = wid & 3;
    int n0   = blockIdx.x * 128;
    int m0   = blockIdx.y * 64;

    float c[2][4][4];
    #pragma unroll
    for (int mf = 0; mf < 2; mf++)
        #pragma unroll
        for (int nf = 0; nf < 4; nf++)
            #pragma unroll
            for (int u = 0; u < 4; u++) c[mf][nf][u] = 0.f;

    int lra = tid >> 2, lca = (tid & 3) * 8;
    int lrb = tid >> 1, lcb = (tid & 1) * 16;
    const float* Xrow = g_at + (size_t)(m0 + lra) * 512 + lca;
    const float* Wrow = W    + (size_t)(n0 + lrb) * 512 + lcb;

    float4 xa[2], wb[4];
    #pragma unroll
    for (int u = 0; u < 2; u++) xa[u] = *(const float4*)(Xrow + u*4);
    #pragma unroll
    for (int u = 0; u < 4; u++) wb[u] = *(const float4*)(Wrow + u*4);
    #pragma unroll
    for (int u = 0; u < 2; u++) {
        As[lra][lca+u*4+0] = f2tf(xa[u].x); As[lra][lca+u*4+1] = f2tf(xa[u].y);
        As[lra][lca+u*4+2] = f2tf(xa[u].z); As[lra][lca+u*4+3] = f2tf(xa[u].w);
    }
    #pragma unroll
    for (int u = 0; u < 4; u++) {
        Bs[lrb][lcb+u*4+0] = f2tf(wb[u].x); Bs[lrb][lcb+u*4+1] = f2tf(wb[u].y);
        Bs[lrb][lcb+u*4+2] = f2tf(wb[u].z); Bs[lrb][lcb+u*4+3] = f2tf(wb[u].w);
    }
    __syncthreads();

    for (int k0 = 0; k0 < 512; k0 += 32) {
        int kn = k0 + 32;
        if (kn < 512) {
            #pragma unroll
            for (int u = 0; u < 2; u++) xa[u] = *(const float4*)(Xrow + kn + u*4);
            #pragma unroll
            for (int u = 0; u < 4; u++) wb[u] = *(const float4*)(Wrow + kn + u*4);
        }
        #pragma unroll
        for (int k8 = 0; k8 < 32; k8 += 8) {
            uint32_t a[2][4], b[4][2];
            #pragma unroll
            for (int mf = 0; mf < 2; mf++) {
                int r = wm*32 + mf*16 + g;
                a[mf][0] = As[r][k8+t];     a[mf][1] = As[r+8][k8+t];
                a[mf][2] = As[r][k8+t+4];   a[mf][3] = As[r+8][k8+t+4];
            }
            #pragma unroll
            for (int nf = 0; nf < 4; nf++) {
                int rn = wn*32 + nf*8 + g;
                b[nf][0] = Bs[rn][k8+t];    b[nf][1] = Bs[rn][k8+t+4];
            }
            #pragma unroll
            for (int mf = 0; mf < 2; mf++)
                #pragma unroll
                for (int nf = 0; nf < 4; nf++)
                    mma8(c[mf][nf], a[mf], b[nf]);
        }
        __syncthreads();
        if (kn < 512) {
            #pragma unroll
            for (int u = 0; u < 2; u++) {
                As[lra][lca+u*4+0] = f2tf(xa[u].x); As[lra][lca+u*4+1] = f2tf(xa[u].y);
                As[lra][lca+u*4+2] = f2tf(xa[u].z); As[lra][lca+u*4+3] = f2tf(xa[u].w);
            }
            #pragma unroll
            for (int u = 0; u < 4; u++) {
                Bs[lrb][lcb+u*4+0] = f2tf(wb[u].x); Bs[lrb][lcb+u*4+1] = f2tf(wb[u].y);
                Bs[lrb][lcb+u*4+2] = f2tf(wb[u].z); Bs[lrb][lcb+u*4+3] = f2tf(wb[u].w);
            }
            __syncthreads();
        }
    }

    #pragma unroll
    for (int nf = 0; nf < 4; nf++) {
        int col = n0 + wn*32 + nf*8 + t*2;
        float bce = bias[col], bco = bias[col+1];
        #pragma unroll
        for (int mf = 0; mf < 2; mf++) {
            #pragma unroll
            for (int half = 0; half < 2; half++) {
                int row = m0 + wm*32 + mf*16 + g + half*8;
                *(float2*)(out + (size_t)row*512 + col)
                    = make_float2(c[mf][nf][half*2+0] + bce, c[mf][nf][half*2+1] + bco);
            }
        }
    }
}

// ---------------- causal score GEMM (packed triangular grid) ------------------
// grid (136, 16): linear tile l -> (qt, kt) lower-triangle decode.
__global__ __launch_bounds__(256) void score_kernel()
{
    int l  = blockIdx.x;
    int bh = blockIdx.y;
    int qt = (int)((sqrtf(8.f * (float)l + 1.f) - 1.f) * 0.5f);
    while ((qt + 1) * (qt + 2) / 2 <= l) qt++;
    while (qt * (qt + 1) / 2 > l) qt--;
    int kt = l - qt * (qt + 1) / 2;

    __shared__ uint32_t Qs[128][36];
    __shared__ uint32_t Ks[128][36];

    const uint32_t* qb = (const uint32_t*)g_qh + (size_t)bh * SS * DKK;
    const uint32_t* kb = (const uint32_t*)g_kh + (size_t)bh * SS * DKK;

    int tid  = threadIdx.x;
    int wid  = tid >> 5, lane = tid & 31;
    int g    = lane >> 2, t = lane & 3;
    int wm   = wid >> 2, wn = wid & 3;
    int i0   = qt * 128, j0 = kt * 128;

    float c[4][4][4];
    #pragma unroll
    for (int mf = 0; mf < 4; mf++)
        #pragma unroll
        for (int nf = 0; nf < 4; nf++)
            #pragma unroll
            for (int u = 0; u < 4; u++) c[mf][nf][u] = 0.f;

    int lr = tid >> 1;
    int lc = (tid & 1) * 16;

    uint4 qv[4], kv[4];
    #pragma unroll
    for (int u = 0; u < 4; u++) {
        qv[u] = *(const uint4*)(qb + (size_t)(i0 + lr) * 64 + lc + u*4);
        kv[u] = *(const uint4*)(kb + (size_t)(j0 + lr) * 64 + lc + u*4);
    }
    #pragma unroll
    for (int u = 0; u < 4; u++) {
        *(uint4*)&Qs[lr][lc+u*4] = qv[u];
        *(uint4*)&Ks[lr][lc+u*4] = kv[u];
    }
    __syncthreads();

    #pragma unroll
    for (int k0 = 0; k0 < 64; k0 += 32) {
        int kn = k0 + 32;
        if (kn < 64) {
            #pragma unroll
            for (int u = 0; u < 4; u++) {
                qv[u] = *(const uint4*)(qb + (size_t)(i0 + lr) * 64 + kn + lc + u*4);
                kv[u] = *(const uint4*)(kb + (size_t)(j0 + lr) * 64 + kn + lc + u*4);
            }
        }
        #pragma unroll
        for (int k8 = 0; k8 < 32; k8 += 8) {
            uint32_t a[4][4], b[4][2];
            #pragma unroll
            for (int mf = 0; mf < 4; mf++) {
                int r = wm*64 + mf*16 + g;
                a[mf][0] = Qs[r][k8+t];     a[mf][1] = Qs[r+8][k8+t];
                a[mf][2] = Qs[r][k8+t+4];   a[mf][3] = Qs[r+8][k8+t+4];
            }
            #pragma unroll
            for (int nf = 0; nf < 4; nf++) {
                int rn = wn*32 + nf*8 + g;
                b[nf][0] = Ks[rn][k8+t];    b[nf][1] = Ks[rn][k8+t+4];
            }
            #pragma unroll
            for (int mf = 0; mf < 4; mf++)
                #pragma unroll
                for (int nf = 0; nf < 4; nf++)
                    mma8(c[mf][nf], a[mf], b[nf]);
        }
        __syncthreads();
        if (kn < 64) {
            #pragma unroll
            for (int u = 0; u < 4; u++) {
                *(uint4*)&Qs[lr][lc+u*4] = qv[u];
                *(uint4*)&Ks[lr][lc+u*4] = kv[u];
            }
            __syncthreads();
        }
    }

    float* C = g_sc + (size_t)bh * SS * SS;
    #pragma unroll
    for (int nf = 0; nf < 4; nf++) {
        int col = j0 + wn*32 + nf*8 + t*2;
        #pragma unroll
        for (int mf = 0; mf < 4; mf++) {
            #pragma unroll
            for (int half = 0; half < 2; half++) {
                int row = i0 + wm*64 + mf*16 + g + half*8;
                *(float2*)(C + (size_t)row*SS + col)
                    = make_float2(c[mf][nf][half*2+0], c[mf][nf][half*2+1]);
            }
        }
    }
}

// ---------------- per-row decay softmax (antidiagonal pairing, 288 thr) ------
__global__ __launch_bounds__(288) void row_kernel(const float* __restrict__ gammas)
{
    __shared__ float part[2][9];
    int rid = blockIdx.x;
    int bh  = rid >> 10;
    int ii  = rid & 1023;
    int h   = bh & (HH - 1);
    int tid = threadIdx.x, wid = tid >> 5, lane = tid & 31;

    int rA   = ii;
    int limA = ((rA >> 7) + 1) << 7;
    int wA   = (limA + 255) >> 8;

    int isB = (wid >= wA) ? 1 : 0;
    int i   = isB ? (SS - 1 - ii) : rA;
    int lw  = isB ? (wid - wA) : wid;
    int lim = ((i >> 7) + 1) << 7;
    int nw  = (lim + 255) >> 8;

    float* row = g_sc + (size_t)bh * SS * SS + (size_t)i * SS;
    const int base = lw * 256 + lane * 8;
    const bool zero_row = (i == 0);

    float sv[8];
    float epre[8];
    float run = 0.f;
    if (!zero_row) {
        float4 v0 = *(const float4*)(row + base);
        float4 v1 = *(const float4*)(row + base + 4);
        float tmp[8] = {v0.x, v0.y, v0.z, v0.w, v1.x, v1.y, v1.z, v1.w};
        #pragma unroll
        for (int u = 0; u < 8; u++) {
            sv[u] = (base + u <= i) ? tmp[u] : -3.0e38f;
            run  += __expf(sv[u]);
            epre[u] = run;
        }
    }

    float x = run;
    #pragma unroll
    for (int d = 1; d < 32; d <<= 1) {
        float y = __shfl_up_sync(0xffffffffu, x, d);
        if (lane >= d) x += y;
    }
    if (lane == 31) part[isB][lw] = x;
    __syncthreads();

    if (zero_row) {
        if (lane < 32) ((float4*)row)[lane] = make_float4(0.f, 0.f, 0.f, 0.f);
        return;
    }

    float offw = 0.f, l1 = 0.f;
    #pragma unroll
    for (int w = 0; w < 8; w++) {
        float p = (w < nw) ? part[isB][w] : 0.f;
        if (w < lw) offw += p;
        l1 += p;
    }
    float off = offw + (x - run);

    float gam = gammas[h * SS + i];
    float sp  = (gam > 20.f) ? gam : log1pf(__expf(gam));
    float gg  = -sp;
    float inv_l1 = 1.f / l1;
    float fi  = (float)i - (float)base;

    uint32_t e2[8];
    #pragma unroll
    for (int u = 0; u < 8; u++) {
        float suffix = l1 - (off + epre[u]);
        float dsq    = suffix * inv_l1 * (fi - (float)u);
        float dist   = sqrtf(fmaxf(dsq, 0.f));
        float eff    = fmaxf(__expf(dist * gg), 1e-5f);
        e2[u] = f2tf(__expf(eff * sv[u]));
    }
    if (base < lim) {
        *(uint4*)(row + base)     = make_uint4(e2[0], e2[1], e2[2], e2[3]);
        *(uint4*)(row + base + 4) = make_uint4(e2[4], e2[5], e2[6], e2[7]);
    }
}

// ---------------- causal PV GEMM O = P @ V (64-row tiles, 512 CTAs) -----------
__global__ __launch_bounds__(256) void pv_kernel()
{
    int mt = (int)gridDim.x - 1 - (int)blockIdx.x;   // longest-k tiles first
    int bh = blockIdx.y;
    int qt = mt >> 1;
    int m0 = mt * 64;

    __shared__ uint32_t Ps[64][36];
    __shared__ uint32_t Vs[64][36];
    __shared__ float    sl2[256];

    const uint32_t* P  = (const uint32_t*)g_sc + (size_t)bh * SS * SS;
    const uint32_t* vb = (const uint32_t*)g_vt + (size_t)bh * DKK * SS;

    int tid  = threadIdx.x;
    int wid  = tid >> 5, lane = tid & 31;
    int g    = lane >> 2, t = lane & 3;
    int wm   = wid >> 1, wn = wid & 1;

    float c[4][4];
    #pragma unroll
    for (int nf = 0; nf < 4; nf++)
        #pragma unroll
        for (int u = 0; u < 4; u++) c[nf][u] = 0.f;

    int lr = tid >> 2;
    int lc = (tid & 3) * 8;
    int kmax = (qt + 1) * 128;
    const uint32_t* Prow = P + (size_t)(m0 + lr) * SS + lc;
    const uint32_t* Vrow = vb + (size_t)lr * SS + lc;

    float l2acc = 0.f;

    uint4 pv[2], vv[2];
    pv[0] = *(const uint4*)(Prow);
    pv[1] = *(const uint4*)(Prow + 4);
    vv[0] = *(const uint4*)(Vrow);
    vv[1] = *(const uint4*)(Vrow + 4);

    #pragma unroll
    for (int u = 0; u < 2; u++) {
        *(uint4*)&Ps[lr][lc + u*4] = pv[u];
        *(uint4*)&Vs[lr][lc + u*4] = vv[u];
        l2acc += __uint_as_float(pv[u].x) + __uint_as_float(pv[u].y)
               + __uint_as_float(pv[u].z) + __uint_as_float(pv[u].w);
    }
    __syncthreads();

    for (int k0 = 0; k0 < kmax; k0 += 32) {
        int kn = k0 + 32;
        if (kn < kmax) {
            pv[0] = *(const uint4*)(Prow + kn);
            pv[1] = *(const uint4*)(Prow + kn + 4);
            vv[0] = *(const uint4*)(Vrow + kn);
            vv[1] = *(const uint4*)(Vrow + kn + 4);
        }
        #pragma unroll
        for (int k8 = 0; k8 < 32; k8 += 8) {
            uint32_t a[4], b[4][2];
            int r = wm*16 + g;
            a[0] = Ps[r][k8+t];     a[1] = Ps[r+8][k8+t];
            a[2] = Ps[r][k8+t+4];   a[3] = Ps[r+8][k8+t+4];
            #pragma unroll
            for (int nf = 0; nf < 4; nf++) {
                int rn = wn*32 + nf*8 + g;
                b[nf][0] = Vs[rn][k8+t];    b[nf][1] = Vs[rn][k8+t+4];
            }
            #pragma unroll
            for (int nf = 0; nf < 4; nf++)
                mma8(c[nf], a, b[nf]);
        }
        __syncthreads();
        if (kn < kmax) {
            #pragma unroll
            for (int u = 0; u < 2; u++) {
                *(uint4*)&Ps[lr][lc + u*4] = pv[u];
                *(uint4*)&Vs[lr][lc + u*4] = vv[u];
                l2acc += __uint_as_float(pv[u].x) + __uint_as_float(pv[u].y)
                       + __uint_as_float(pv[u].z) + __uint_as_float(pv[u].w);
            }
            __syncthreads();
        }
    }

    sl2[lr*4 + (tid & 3)] = l2acc;
    __syncthreads();

    int b = bh >> 3, h = bh & 7;
    #pragma unroll
    for (int half = 0; half < 2; half++) {
        int sl = wm*16 + g + half*8;
        int s  = m0 + sl;
        float l2v = sl2[sl*4] + sl2[sl*4+1] + sl2[sl*4+2] + sl2[sl*4+3];
        float sc  = (s == 0) ? 0.f : 1.f / l2v;
        #pragma unroll
        for (int nf = 0; nf < 4; nf++) {
            int dk = wn*32 + nf*8 + t*2;
            *(float2*)(g_at + ((size_t)b * SS + s) * DD + h*64 + dk)
                = make_float2(c[nf][half*2+0] * sc, c[nf][half*2+1] * sc);
        }
    }
}

// ---------------- launcher ----------------------------------------------------
extern "C" void kernel_launch(void* const* d_in, const int* in_sizes, int n_in,
                              void* d_out, int out_size)
{
    const float* q      = (const float*)d_in[0];
    const float* k      = (const float*)d_in[1];
    const float* v      = (const float*)d_in[2];
    const float* Wq     = (const float*)d_in[5];
    const float* bq     = (const float*)d_in[6];
    const float* Wk     = (const float*)d_in[7];
    const float* bk     = (const float*)d_in[8];
    const float* Wv     = (const float*)d_in[9];
    const float* bv     = (const float*)d_in[10];
    const float* Wo     = (const float*)d_in[11];
    const float* bo     = (const float*)d_in[12];
    const float* gammas = (const float*)d_in[13];
    float* out = (float*)d_out;

    rope_tab_kernel<<<(SS * 32 + 255) / 256, 256>>>();
    proj_kernel<<<dim3(4, 32, 3), 256>>>(q, k, v, Wq, bq, Wk, bk, Wv, bv);
    score_kernel<<<dim3(136, 16), 256>>>();
    row_kernel<<<BHH * (SS/2), 288>>>(gammas);
    pv_kernel<<<dim3(32, 16), 256>>>();
    out_proj_kernel<<<dim3(4, 64), 256>>>(Wo, bo, out);
}

// round 17
// speedup vs baseline: 1.0119x; 1.0119x over previous
#include <cuda_runtime.h>
#include <math.h>
#include <stdint.h>

#define BB   2
#define SS   2048
#define DD   512
#define HH   8
#define DKK  64
#define BHH  (BB*HH)

// ---------------- scratch (device globals; no allocation allowed) ----------
__device__ float g_qh[BHH*SS*DKK];          // [bh][s][dk] tf32 bits, pre-scaled 1/8
__device__ float g_kh[BHH*SS*DKK];          // tf32 bits
__device__ float g_vt[BHH*DKK*SS];          // V^T [bh][dk][s], tf32 bits
__device__ float g_at[BB*SS*DD];            // attention out [b][s][h*64+dk]
__device__ float g_cos[SS*DKK];
__device__ float g_sin[SS*DKK];
__device__ float g_sc[67108864];            // scores -> unnormalized P (tf32 bits)

// ---------------- helpers ----------------------------------------------------
__device__ __forceinline__ uint32_t f2tf(float f)
{
    uint32_t u;
    asm("cvt.rna.tf32.f32 %0, %1;" : "=r"(u) : "f"(f));
    return u;
}

__device__ __forceinline__ void mma8(float* c, const uint32_t* a, const uint32_t* b)
{
    asm volatile(
        "mma.sync.aligned.m16n8k8.row.col.f32.tf32.tf32.f32 "
        "{%0,%1,%2,%3}, {%4,%5,%6,%7}, {%8,%9}, {%0,%1,%2,%3};\n"
        : "+f"(c[0]), "+f"(c[1]), "+f"(c[2]), "+f"(c[3])
        : "r"(a[0]), "r"(a[1]), "r"(a[2]), "r"(a[3]), "r"(b[0]), "r"(b[1]));
}

// ---------------- RoPE table ------------------------------------------------
__global__ void rope_tab_kernel()
{
    int idx = blockIdx.x * blockDim.x + threadIdx.x;
    if (idx >= SS * 32) return;
    int s = idx >> 5;
    int m = idx & 31;
    float f = (float)s * powf(10000.f, -(float)(2 * m) / 64.f);
    float sn, cs;
    sincosf(f, &sn, &cs);
    g_cos[s*64 + 2*m]     = cs;
    g_cos[s*64 + 2*m + 1] = cs;
    g_sin[s*64 + 2*m]     = sn;
    g_sin[s*64 + 2*m + 1] = sn;
}

// ---------------- fused QKV projection + RoPE (tf32 mma, staged q/k) ---------
#define AS(r, cc) sbuf[(r)*36 + (cc)]
#define BS(r, cc) sbuf[128*36 + (r)*36 + (cc)]

__global__ __launch_bounds__(256) void proj_kernel(
    const float* __restrict__ qx, const float* __restrict__ kx, const float* __restrict__ vx,
    const float* __restrict__ Wq, const float* __restrict__ bq,
    const float* __restrict__ Wk, const float* __restrict__ bk,
    const float* __restrict__ Wv, const float* __restrict__ bv)
{
    __shared__ uint32_t sbuf[2*128*36];   // As/Bs in mainloop; q/k staging after

    int which = blockIdx.z;
    const float* X    = (which == 0) ? qx : (which == 1) ? kx : vx;
    const float* W    = (which == 0) ? Wq : (which == 1) ? Wk : Wv;
    const float* bias = (which == 0) ? bq : (which == 1) ? bk : bv;

    int tid  = threadIdx.x;
    int wid  = tid >> 5, lane = tid & 31;
    int g    = lane >> 2, t = lane & 3;
    int wm   = wid >> 2, wn = wid & 3;
    int n0   = blockIdx.x * 128;
    int m0   = blockIdx.y * 128;

    float c[4][4][4];
    #pragma unroll
    for (int mf = 0; mf < 4; mf++)
        #pragma unroll
        for (int nf = 0; nf < 4; nf++)
            #pragma unroll
            for (int u = 0; u < 4; u++) c[mf][nf][u] = 0.f;

    int lr = tid >> 1;
    int lc = (tid & 1) * 16;

    float4 xa[4], wb[4];
    #pragma unroll
    for (int u = 0; u < 4; u++) {
        xa[u] = *(const float4*)(X + (size_t)(m0 + lr) * 512 + lc + u*4);
        wb[u] = *(const float4*)(W + (size_t)(n0 + lr) * 512 + lc + u*4);
    }
    #pragma unroll
    for (int u = 0; u < 4; u++) {
        AS(lr, lc+u*4+0) = f2tf(xa[u].x); AS(lr, lc+u*4+1) = f2tf(xa[u].y);
        AS(lr, lc+u*4+2) = f2tf(xa[u].z); AS(lr, lc+u*4+3) = f2tf(xa[u].w);
        BS(lr, lc+u*4+0) = f2tf(wb[u].x); BS(lr, lc+u*4+1) = f2tf(wb[u].y);
        BS(lr, lc+u*4+2) = f2tf(wb[u].z); BS(lr, lc+u*4+3) = f2tf(wb[u].w);
    }
    __syncthreads();

    for (int k0 = 0; k0 < 512; k0 += 32) {
        int kn = k0 + 32;
        if (kn < 512) {
            #pragma unroll
            for (int u = 0; u < 4; u++) {
                xa[u] = *(const float4*)(X + (size_t)(m0 + lr) * 512 + kn + lc + u*4);
                wb[u] = *(const float4*)(W + (size_t)(n0 + lr) * 512 + kn + lc + u*4);
            }
        }
        #pragma unroll
        for (int k8 = 0; k8 < 32; k8 += 8) {
            uint32_t a[4][4], b[4][2];
            #pragma unroll
            for (int mf = 0; mf < 4; mf++) {
                int r = wm*64 + mf*16 + g;
                a[mf][0] = AS(r, k8+t);     a[mf][1] = AS(r+8, k8+t);
                a[mf][2] = AS(r, k8+t+4);   a[mf][3] = AS(r+8, k8+t+4);
            }
            #pragma unroll
            for (int nf = 0; nf < 4; nf++) {
                int rn = wn*32 + nf*8 + g;
                b[nf][0] = BS(rn, k8+t);    b[nf][1] = BS(rn, k8+t+4);
            }
            #pragma unroll
            for (int mf = 0; mf < 4; mf++)
                #pragma unroll
                for (int nf = 0; nf < 4; nf++)
                    mma8(c[mf][nf], a[mf], b[nf]);
        }
        __syncthreads();
        if (kn < 512) {
            #pragma unroll
            for (int u = 0; u < 4; u++) {
                AS(lr, lc+u*4+0) = f2tf(xa[u].x); AS(lr, lc+u*4+1) = f2tf(xa[u].y);
                AS(lr, lc+u*4+2) = f2tf(xa[u].z); AS(lr, lc+u*4+3) = f2tf(xa[u].w);
                BS(lr, lc+u*4+0) = f2tf(wb[u].x); BS(lr, lc+u*4+1) = f2tf(wb[u].y);
                BS(lr, lc+u*4+2) = f2tf(wb[u].z); BS(lr, lc+u*4+3) = f2tf(wb[u].w);
            }
            __syncthreads();
        }
    }

    if (which == 2) {
        // ---- v epilogue: direct transposed store ----
        #pragma unroll
        for (int nf = 0; nf < 4; nf++) {
            int col = n0 + wn*32 + nf*8 + t*2;
            int hh  = col >> 6, dk = col & 63;
            float bce = bias[col], bco = bias[col+1];
            #pragma unroll
            for (int mf = 0; mf < 4; mf++) {
                #pragma unroll
                for (int half = 0; half < 2; half++) {
                    int row  = m0 + wm*64 + mf*16 + g + half*8;
                    int srow = row & (SS-1);
                    int bidx = row >> 11;
                    float e = c[mf][nf][half*2+0] + bce;
                    float o = c[mf][nf][half*2+1] + bco;
                    size_t vb = (size_t)(bidx*HH + hh) * DKK;
                    g_vt[(vb + dk    )*SS + srow] = __uint_as_float(f2tf(e));
                    g_vt[(vb + dk + 1)*SS + srow] = __uint_as_float(f2tf(o));
                }
            }
        }
    } else {
        // ---- q/k epilogue: rope + tf32 into smem stage, coalesced store ----
        float* stage = (float*)sbuf;          // [64][132]
        float* Y = (which == 0) ? g_qh : g_kh;
        float sc = (which == 0) ? 0.125f : 1.0f;

        #pragma unroll
        for (int p = 0; p < 2; p++) {
            __syncthreads();
            if (wm == p) {
                #pragma unroll
                for (int nf = 0; nf < 4; nf++) {
                    int coll = wn*32 + nf*8 + t*2;
                    int col  = n0 + coll;
                    int dk   = col & 63;
                    float bce = bias[col], bco = bias[col+1];
                    #pragma unroll
                    for (int mf = 0; mf < 4; mf++) {
                        #pragma unroll
                        for (int half = 0; half < 2; half++) {
                            int rl   = mf*16 + g + half*8;     // 0..63
                            int srow = (m0 + p*64 + rl) & (SS-1);
                            float e = c[mf][nf][half*2+0] + bce;
                            float o = c[mf][nf][half*2+1] + bco;
                            float cs = g_cos[srow*64 + dk];
                            float sn = g_sin[srow*64 + dk];
                            float ne = __uint_as_float(f2tf((e*cs - o*sn) * sc));
                            float no = __uint_as_float(f2tf((o*cs + e*sn) * sc));
                            *(float2*)&stage[rl*132 + coll] = make_float2(ne, no);
                        }
                    }
                }
            }
            __syncthreads();
            int r   = tid & 63;
            int seg = tid >> 6;
            int row  = m0 + p*64 + r;
            int srow = row & (SS-1);
            int bidx = row >> 11;
            int head = (n0 >> 6) + (seg >> 1);
            float* dst = Y + ((size_t)(bidx*HH + head)*SS + srow)*DKK + (seg & 1)*32;
            const float* src = stage + r*132 + seg*32;
            #pragma unroll
            for (int w = 0; w < 8; w++)
                ((float4*)dst)[w] = ((const float4*)src)[w];
        }
    }
}

// ---------------- output projection (tf32 mma, 128-row tiles, reg-prefetch) --
__global__ __launch_bounds__(256) void out_proj_kernel(
    const float* __restrict__ W, const float* __restrict__ bias, float* __restrict__ out)
{
    __shared__ uint32_t As[128][36];
    __shared__ uint32_t Bs[128][36];

    int tid  = threadIdx.x;
    int wid  = tid >> 5, lane = tid & 31;
    int g    = lane >> 2, t = lane & 3;
    int wm   = wid >> 2, wn = wid & 3;
    int n0   = blockIdx.x * 128;
    int m0   = blockIdx.y * 128;

    float c[4][4][4];
    #pragma unroll
    for (int mf = 0; mf < 4; mf++)
        #pragma unroll
        for (int nf = 0; nf < 4; nf++)
            #pragma unroll
            for (int u = 0; u < 4; u++) c[mf][nf][u] = 0.f;

    int lr = tid >> 1;
    int lc = (tid & 1) * 16;

    float4 xa[4], wb[4];
    #pragma unroll
    for (int u = 0; u < 4; u++) {
        xa[u] = *(const float4*)(g_at + (size_t)(m0 + lr) * 512 + lc + u*4);
        wb[u] = *(const float4*)(W    + (size_t)(n0 + lr) * 512 + lc + u*4);
    }
    #pragma unroll
    for (int u = 0; u < 4; u++) {
        As[lr][lc+u*4+0] = f2tf(xa[u].x); As[lr][lc+u*4+1] = f2tf(xa[u].y);
        As[lr][lc+u*4+2] = f2tf(xa[u].z); As[lr][lc+u*4+3] = f2tf(xa[u].w);
        Bs[lr][lc+u*4+0] = f2tf(wb[u].x); Bs[lr][lc+u*4+1] = f2tf(wb[u].y);
        Bs[lr][lc+u*4+2] = f2tf(wb[u].z); Bs[lr][lc+u*4+3] = f2tf(wb[u].w);
    }
    __syncthreads();

    for (int k0 = 0; k0 < 512; k0 += 32) {
        int kn = k0 + 32;
        if (kn < 512) {
            #pragma unroll
            for (int u = 0; u < 4; u++) {
                xa[u] = *(const float4*)(g_at + (size_t)(m0 + lr) * 512 + kn + lc + u*4);
                wb[u] = *(const float4*)(W    + (size_t)(n0 + lr) * 512 + kn + lc + u*4);
            }
        }
        #pragma unroll
        for (int k8 = 0; k8 < 32; k8 += 8) {
            uint32_t a[4][4], b[4][2];
            #pragma unroll
            for (int mf = 0; mf < 4; mf++) {
                int r = wm*64 + mf*16 + g;
                a[mf][0] = As[r][k8+t];     a[mf][1] = As[r+8][k8+t];
                a[mf][2] = As[r][k8+t+4];   a[mf][3] = As[r+8][k8+t+4];
            }
            #pragma unroll
            for (int nf = 0; nf < 4; nf++) {
                int rn = wn*32 + nf*8 + g;
                b[nf][0] = Bs[rn][k8+t];    b[nf][1] = Bs[rn][k8+t+4];
            }
            #pragma unroll
            for (int mf = 0; mf < 4; mf++)
                #pragma unroll
                for (int nf = 0; nf < 4; nf++)
                    mma8(c[mf][nf], a[mf], b[nf]);
        }
        __syncthreads();
        if (kn < 512) {
            #pragma unroll
            for (int u = 0; u < 4; u++) {
                As[lr][lc+u*4+0] = f2tf(xa[u].x); As[lr][lc+u*4+1] = f2tf(xa[u].y);
                As[lr][lc+u*4+2] = f2tf(xa[u].z); As[lr][lc+u*4+3] = f2tf(xa[u].w);
                Bs[lr][lc+u*4+0] = f2tf(wb[u].x); Bs[lr][lc+u*4+1] = f2tf(wb[u].y);
                Bs[lr][lc+u*4+2] = f2tf(wb[u].z); Bs[lr][lc+u*4+3] = f2tf(wb[u].w);
            }
            __syncthreads();
        }
    }

    #pragma unroll
    for (int nf = 0; nf < 4; nf++) {
        int col = n0 + wn*32 + nf*8 + t*2;
        float bce = bias[col], bco = bias[col+1];
        #pragma unroll
        for (int mf = 0; mf < 4; mf++) {
            #pragma unroll
            for (int half = 0; half < 2; half++) {
                int row = m0 + wm*64 + mf*16 + g + half*8;
                *(float2*)(out + (size_t)row*512 + col)
                    = make_float2(c[mf][nf][half*2+0] + bce, c[mf][nf][half*2+1] + bco);
            }
        }
    }
}

// ---------------- causal score GEMM (packed triangular grid) ------------------
// grid (136, 16): linear tile l -> (qt, kt) lower-triangle decode.
__global__ __launch_bounds__(256) void score_kernel()
{
    int l  = blockIdx.x;
    int bh = blockIdx.y;
    int qt = (int)((sqrtf(8.f * (float)l + 1.f) - 1.f) * 0.5f);
    while ((qt + 1) * (qt + 2) / 2 <= l) qt++;
    while (qt * (qt + 1) / 2 > l) qt--;
    int kt = l - qt * (qt + 1) / 2;

    __shared__ uint32_t Qs[128][36];
    __shared__ uint32_t Ks[128][36];

    const uint32_t* qb = (const uint32_t*)g_qh + (size_t)bh * SS * DKK;
    const uint32_t* kb = (const uint32_t*)g_kh + (size_t)bh * SS * DKK;

    int tid  = threadIdx.x;
    int wid  = tid >> 5, lane = tid & 31;
    int g    = lane >> 2, t = lane & 3;
    int wm   = wid >> 2, wn = wid & 3;
    int i0   = qt * 128, j0 = kt * 128;

    float c[4][4][4];
    #pragma unroll
    for (int mf = 0; mf < 4; mf++)
        #pragma unroll
        for (int nf = 0; nf < 4; nf++)
            #pragma unroll
            for (int u = 0; u < 4; u++) c[mf][nf][u] = 0.f;

    int lr = tid >> 1;
    int lc = (tid & 1) * 16;

    uint4 qv[4], kv[4];
    #pragma unroll
    for (int u = 0; u < 4; u++) {
        qv[u] = *(const uint4*)(qb + (size_t)(i0 + lr) * 64 + lc + u*4);
        kv[u] = *(const uint4*)(kb + (size_t)(j0 + lr) * 64 + lc + u*4);
    }
    #pragma unroll
    for (int u = 0; u < 4; u++) {
        *(uint4*)&Qs[lr][lc+u*4] = qv[u];
        *(uint4*)&Ks[lr][lc+u*4] = kv[u];
    }
    __syncthreads();

    #pragma unroll
    for (int k0 = 0; k0 < 64; k0 += 32) {
        int kn = k0 + 32;
        if (kn < 64) {
            #pragma unroll
            for (int u = 0; u < 4; u++) {
                qv[u] = *(const uint4*)(qb + (size_t)(i0 + lr) * 64 + kn + lc + u*4);
                kv[u] = *(const uint4*)(kb + (size_t)(j0 + lr) * 64 + kn + lc + u*4);
            }
        }
        #pragma unroll
        for (int k8 = 0; k8 < 32; k8 += 8) {
            uint32_t a[4][4], b[4][2];
            #pragma unroll
            for (int mf = 0; mf < 4; mf++) {
                int r = wm*64 + mf*16 + g;
                a[mf][0] = Qs[r][k8+t];     a[mf][1] = Qs[r+8][k8+t];
                a[mf][2] = Qs[r][k8+t+4];   a[mf][3] = Qs[r+8][k8+t+4];
            }
            #pragma unroll
            for (int nf = 0; nf < 4; nf++) {
                int rn = wn*32 + nf*8 + g;
                b[nf][0] = Ks[rn][k8+t];    b[nf][1] = Ks[rn][k8+t+4];
            }
            #pragma unroll
            for (int mf = 0; mf < 4; mf++)
                #pragma unroll
                for (int nf = 0; nf < 4; nf++)
                    mma8(c[mf][nf], a[mf], b[nf]);
        }
        __syncthreads();
        if (kn < 64) {
            #pragma unroll
            for (int u = 0; u < 4; u++) {
                *(uint4*)&Qs[lr][lc+u*4] = qv[u];
                *(uint4*)&Ks[lr][lc+u*4] = kv[u];
            }
            __syncthreads();
        }
    }

    float* C = g_sc + (size_t)bh * SS * SS;
    #pragma unroll
    for (int nf = 0; nf < 4; nf++) {
        int col = j0 + wn*32 + nf*8 + t*2;
        #pragma unroll
        for (int mf = 0; mf < 4; mf++) {
            #pragma unroll
            for (int half = 0; half < 2; half++) {
                int row = i0 + wm*64 + mf*16 + g + half*8;
                *(float2*)(C + (size_t)row*SS + col)
                    = make_float2(c[mf][nf][half*2+0], c[mf][nf][half*2+1]);
            }
        }
    }
}

// ---------------- per-row decay softmax (antidiagonal pairing, 288 thr) ------
__global__ __launch_bounds__(288) void row_kernel(const float* __restrict__ gammas)
{
    __shared__ float part[2][9];
    int rid = blockIdx.x;
    int bh  = rid >> 10;
    int ii  = rid & 1023;
    int h   = bh & (HH - 1);
    int tid = threadIdx.x, wid = tid >> 5, lane = tid & 31;

    int rA   = ii;
    int limA = ((rA >> 7) + 1) << 7;
    int wA   = (limA + 255) >> 8;

    int isB = (wid >= wA) ? 1 : 0;
    int i   = isB ? (SS - 1 - ii) : rA;
    int lw  = isB ? (wid - wA) : wid;
    int lim = ((i >> 7) + 1) << 7;
    int nw  = (lim + 255) >> 8;

    float* row = g_sc + (size_t)bh * SS * SS + (size_t)i * SS;
    const int base = lw * 256 + lane * 8;
    const bool zero_row = (i == 0);

    float sv[8];
    float epre[8];
    float run = 0.f;
    if (!zero_row) {
        float4 v0 = *(const float4*)(row + base);
        float4 v1 = *(const float4*)(row + base + 4);
        float tmp[8] = {v0.x, v0.y, v0.z, v0.w, v1.x, v1.y, v1.z, v1.w};
        #pragma unroll
        for (int u = 0; u < 8; u++) {
            sv[u] = (base + u <= i) ? tmp[u] : -3.0e38f;
            run  += __expf(sv[u]);
            epre[u] = run;
        }
    }

    float x = run;
    #pragma unroll
    for (int d = 1; d < 32; d <<= 1) {
        float y = __shfl_up_sync(0xffffffffu, x, d);
        if (lane >= d) x += y;
    }
    if (lane == 31) part[isB][lw] = x;
    __syncthreads();

    if (zero_row) {
        if (lane < 32) ((float4*)row)[lane] = make_float4(0.f, 0.f, 0.f, 0.f);
        return;
    }

    float offw = 0.f, l1 = 0.f;
    #pragma unroll
    for (int w = 0; w < 8; w++) {
        float p = (w < nw) ? part[isB][w] : 0.f;
        if (w < lw) offw += p;
        l1 += p;
    }
    float off = offw + (x - run);

    float gam = gammas[h * SS + i];
    float sp  = (gam > 20.f) ? gam : log1pf(__expf(gam));
    float gg  = -sp;
    float inv_l1 = 1.f / l1;
    float fi  = (float)i - (float)base;

    uint32_t e2[8];
    #pragma unroll
    for (int u = 0; u < 8; u++) {
        float suffix = l1 - (off + epre[u]);
        float dsq    = suffix * inv_l1 * (fi - (float)u);
        float dist   = sqrtf(fmaxf(dsq, 0.f));
        float eff    = fmaxf(__expf(dist * gg), 1e-5f);
        e2[u] = f2tf(__expf(eff * sv[u]));
    }
    if (base < lim) {
        *(uint4*)(row + base)     = make_uint4(e2[0], e2[1], e2[2], e2[3]);
        *(uint4*)(row + base + 4) = make_uint4(e2[4], e2[5], e2[6], e2[7]);
    }
}

// ---------------- causal PV GEMM O = P @ V (64-row tiles, 512 CTAs) -----------
__global__ __launch_bounds__(256) void pv_kernel()
{
    int mt = (int)gridDim.x - 1 - (int)blockIdx.x;   // longest-k tiles first
    int bh = blockIdx.y;
    int qt = mt >> 1;
    int m0 = mt * 64;

    __shared__ uint32_t Ps[64][36];
    __shared__ uint32_t Vs[64][36];
    __shared__ float    sl2[256];

    const uint32_t* P  = (const uint32_t*)g_sc + (size_t)bh * SS * SS;
    const uint32_t* vb = (const uint32_t*)g_vt + (size_t)bh * DKK * SS;

    int tid  = threadIdx.x;
    int wid  = tid >> 5, lane = tid & 31;
    int g    = lane >> 2, t = lane & 3;
    int wm   = wid >> 1, wn = wid & 1;

    float c[4][4];
    #pragma unroll
    for (int nf = 0; nf < 4; nf++)
        #pragma unroll
        for (int u = 0; u < 4; u++) c[nf][u] = 0.f;

    int lr = tid >> 2;
    int lc = (tid & 3) * 8;
    int kmax = (qt + 1) * 128;
    const uint32_t* Prow = P + (size_t)(m0 + lr) * SS + lc;
    const uint32_t* Vrow = vb + (size_t)lr * SS + lc;

    float l2acc = 0.f;

    uint4 pv[2], vv[2];
    pv[0] = *(const uint4*)(Prow);
    pv[1] = *(const uint4*)(Prow + 4);
    vv[0] = *(const uint4*)(Vrow);
    vv[1] = *(const uint4*)(Vrow + 4);

    #pragma unroll
    for (int u = 0; u < 2; u++) {
        *(uint4*)&Ps[lr][lc + u*4] = pv[u];
        *(uint4*)&Vs[lr][lc + u*4] = vv[u];
        l2acc += __uint_as_float(pv[u].x) + __uint_as_float(pv[u].y)
               + __uint_as_float(pv[u].z) + __uint_as_float(pv[u].w);
    }
    __syncthreads();

    for (int k0 = 0; k0 < kmax; k0 += 32) {
        int kn = k0 + 32;
        if (kn < kmax) {
            pv[0] = *(const uint4*)(Prow + kn);
            pv[1] = *(const uint4*)(Prow + kn + 4);
            vv[0] = *(const uint4*)(Vrow + kn);
            vv[1] = *(const uint4*)(Vrow + kn + 4);
        }
        #pragma unroll
        for (int k8 = 0; k8 < 32; k8 += 8) {
            uint32_t a[4], b[4][2];
            int r = wm*16 + g;
            a[0] = Ps[r][k8+t];     a[1] = Ps[r+8][k8+t];
            a[2] = Ps[r][k8+t+4];   a[3] = Ps[r+8][k8+t+4];
            #pragma unroll
            for (int nf = 0; nf < 4; nf++) {
                int rn = wn*32 + nf*8 + g;
                b[nf][0] = Vs[rn][k8+t];    b[nf][1] = Vs[rn][k8+t+4];
            }
            #pragma unroll
            for (int nf = 0; nf < 4; nf++)
                mma8(c[nf], a, b[nf]);
        }
        __syncthreads();
        if (kn < kmax) {
            #pragma unroll
            for (int u = 0; u < 2; u++) {
                *(uint4*)&Ps[lr][lc + u*4] = pv[u];
                *(uint4*)&Vs[lr][lc + u*4] = vv[u];
                l2acc += __uint_as_float(pv[u].x) + __uint_as_float(pv[u].y)
                       + __uint_as_float(pv[u].z) + __uint_as_float(pv[u].w);
            }
            __syncthreads();
        }
    }

    sl2[lr*4 + (tid & 3)] = l2acc;
    __syncthreads();

    int b = bh >> 3, h = bh & 7;
    #pragma unroll
    for (int half = 0; half < 2; half++) {
        int sl = wm*16 + g + half*8;
        int s  = m0 + sl;
        float l2v = sl2[sl*4] + sl2[sl*4+1] + sl2[sl*4+2] + sl2[sl*4+3];
        float sc  = (s == 0) ? 0.f : 1.f / l2v;
        #pragma unroll
        for (int nf = 0; nf < 4; nf++) {
            int dk = wn*32 + nf*8 + t*2;
            *(float2*)(g_at + ((size_t)b * SS + s) * DD + h*64 + dk)
                = make_float2(c[nf][half*2+0] * sc, c[nf][half*2+1] * sc);
        }
    }
}

// ---------------- launcher ----------------------------------------------------
extern "C" void kernel_launch(void* const* d_in, const int* in_sizes, int n_in,
                              void* d_out, int out_size)
{
    const float* q      = (const float*)d_in[0];
    const float* k      = (const float*)d_in[1];
    const float* v      = (const float*)d_in[2];
    const float* Wq     = (const float*)d_in[5];
    const float* bq     = (const float*)d_in[6];
    const float* Wk     = (const float*)d_in[7];
    const float* bk     = (const float*)d_in[8];
    const float* Wv     = (const float*)d_in[9];
    const float* bv     = (const float*)d_in[10];
    const float* Wo     = (const float*)d_in[11];
    const float* bo     = (const float*)d_in[12];
    const float* gammas = (const float*)d_in[13];
    float* out = (float*)d_out;

    rope_tab_kernel<<<(SS * 32 + 255) / 256, 256>>>();
    proj_kernel<<<dim3(4, 32, 3), 256>>>(q, k, v, Wq, bq, Wk, bk, Wv, bv);
    score_kernel<<<dim3(136, 16), 256>>>();
    row_kernel<<<BHH * (SS/2), 288>>>(gammas);
    pv_kernel<<<dim3(32, 16), 256>>>();
    out_proj_kernel<<<dim3(4, 32), 256>>>(Wo, bo, out);
}